// round 10
// baseline (speedup 1.0000x reference)
#include <cuda_runtime.h>
#include <math.h>

#define BB 16
#define TT 256
#define SS 1024
#define VV 32000
#define MM (BB*TT)            // 4096 rows in the time-major stream
#define NB_RECUR 128
#define OUT_ELEMS 131072000   // B*T*V

typedef unsigned long long ull;

// ---------------- scratch (device globals; no runtime allocation) ----------
__device__ __align__(256) float g_scratch[6 * 4194304 + 2 * 16384];
__device__ volatile unsigned int g_flags[NB_RECUR];

// ---------------- packed f32x2 helpers -------------------------------------
__device__ __forceinline__ void fma2(ull& d, ull a, ull b) {
    asm("fma.rn.f32x2 %0, %1, %2, %0;" : "+l"(d) : "l"(a), "l"(b));
}
__device__ __forceinline__ ull pack2(float x) {
    ull v; asm("mov.b64 %0, {%1, %1};" : "=l"(v) : "f"(x)); return v;
}
__device__ __forceinline__ float2 u2f2(ull v) {
    float2 r; asm("mov.b64 {%0, %1}, %2;" : "=f"(r.x), "=f"(r.y) : "l"(v)); return r;
}

// ---------------------------------------------------------------------------
__global__ void embed_kernel(const int* __restrict__ x,
                             const float* __restrict__ emb,
                             float* __restrict__ X0) {
    int row = blockIdx.x;              // row = t*16 + b
    int t = row >> 4, b = row & 15;
    int id = x[b * TT + t];            // x is [B, T]
    const float4* src = (const float4*)(emb + (size_t)id * SS);
    float4* dst = (float4*)(X0 + (size_t)row * SS);
    dst[threadIdx.x] = src[threadIdx.x];   // 256 thr * 4 = 1024
}

// zero the recurrent state AND the barrier flags (stream-ordered before recur)
__global__ void reset_kernel(float* __restrict__ gh) {
    int i = blockIdx.x * blockDim.x + threadIdx.x;
    if (i < BB * SS) gh[i] = 0.f;
    if (i < NB_RECUR) g_flags[i] = 0u;
}

// h_final[j][b][s] = Hj[(T-1)*16 + b][s]
__global__ void finalh_kernel(const float* __restrict__ H0,
                              const float* __restrict__ H1,
                              float* __restrict__ out) {
    int i = blockIdx.x * 256 + threadIdx.x;      // 0..32767
    const float* H = (i >> 14) ? H1 : H0;
    out[i] = H[(size_t)(TT - 1) * BB * SS + (i & 16383)];
}

// ---------------------------------------------------------------------------
// fp32 GEMM with packed FFMA2: C[M,N] = A[M,K] @ B[K,N] + bias[N]
// BM=BN=128, BK=8, 256 threads, 8x8 per thread (acc paired along columns).
// remap!=0: output row m = t*16+b is written to row (b*T + t) of C.
// ---------------------------------------------------------------------------
__global__ __launch_bounds__(256) void gemm128(
    const float* __restrict__ A, const float* __restrict__ Bm,
    const float* __restrict__ bias, float* __restrict__ C,
    int K, int N, int remap)
{
    __shared__ __align__(16) float As[2][8][128];
    __shared__ __align__(16) float Bs[2][8][128];

    int tid = threadIdx.x;
    int m0 = blockIdx.y * 128, n0 = blockIdx.x * 128;

    int ma = tid >> 1, ka = (tid & 1) * 4;     // A: one float4 per thread
    int kb = tid >> 5, nb4 = (tid & 31) * 4;   // B: one float4 per thread
    const float* Ap = A + (size_t)(m0 + ma) * K + ka;
    const float* Bp = Bm + (size_t)kb * N + n0 + nb4;

    float4 pa = *(const float4*)Ap;
    float4 pb = *(const float4*)Bp;
    As[0][ka + 0][ma] = pa.x; As[0][ka + 1][ma] = pa.y;
    As[0][ka + 2][ma] = pa.z; As[0][ka + 3][ma] = pa.w;
    *(float4*)&Bs[0][kb][nb4] = pb;
    __syncthreads();

    // acc2[i][j2] holds columns (2*j2, 2*j2+1) of row i as packed f32x2
    ull acc2[8][4];
#pragma unroll
    for (int i = 0; i < 8; i++)
#pragma unroll
        for (int j = 0; j < 4; j++) acc2[i][j] = 0ull;

    int ty = tid >> 4, tx = tid & 15;
    int NT = K >> 3;
    int buf = 0;

    for (int kt = 0; kt < NT; kt++) {
        if (kt + 1 < NT) {
            pa = *(const float4*)(Ap + (kt + 1) * 8);
            pb = *(const float4*)(Bp + (size_t)(kt + 1) * 8 * N);
        }
#pragma unroll
        for (int k = 0; k < 8; k++) {
            float4 a0 = *(const float4*)&As[buf][k][ty * 8];
            float4 a1 = *(const float4*)&As[buf][k][ty * 8 + 4];
            const ulonglong2* bsp = (const ulonglong2*)&Bs[buf][k][tx * 8];
            ulonglong2 b01 = bsp[0];         // {b0,b1},{b2,b3}
            ulonglong2 b23 = bsp[1];         // {b4,b5},{b6,b7}
            float av[8] = {a0.x, a0.y, a0.z, a0.w, a1.x, a1.y, a1.z, a1.w};
#pragma unroll
            for (int i = 0; i < 8; i++) {
                ull ap2 = pack2(av[i]);
                fma2(acc2[i][0], ap2, b01.x);
                fma2(acc2[i][1], ap2, b01.y);
                fma2(acc2[i][2], ap2, b23.x);
                fma2(acc2[i][3], ap2, b23.y);
            }
        }
        if (kt + 1 < NT) {
            buf ^= 1;
            As[buf][ka + 0][ma] = pa.x; As[buf][ka + 1][ma] = pa.y;
            As[buf][ka + 2][ma] = pa.z; As[buf][ka + 3][ma] = pa.w;
            *(float4*)&Bs[buf][kb][nb4] = pb;
            __syncthreads();
        }
    }

    // epilogue: bias + optional (t,b)->(b,t) remap
#pragma unroll
    for (int i = 0; i < 8; i++) {
        int m = m0 + ty * 8 + i;
        size_t orow = remap ? (size_t)((m & 15) * TT + (m >> 4)) * N
                            : (size_t)m * N;
        int col = n0 + tx * 8;
        float2 c0 = u2f2(acc2[i][0]);
        float2 c1 = u2f2(acc2[i][1]);
        float2 c2 = u2f2(acc2[i][2]);
        float2 c3 = u2f2(acc2[i][3]);
        float4 o0, o1;
        o0.x = c0.x + bias[col + 0];
        o0.y = c0.y + bias[col + 1];
        o0.z = c1.x + bias[col + 2];
        o0.w = c1.y + bias[col + 3];
        o1.x = c2.x + bias[col + 4];
        o1.y = c2.y + bias[col + 5];
        o1.z = c3.x + bias[col + 6];
        o1.w = c3.y + bias[col + 7];
        *(float4*)(C + orow + col) = o0;
        *(float4*)(C + orow + col + 4) = o1;
    }
}

// ---------------------------------------------------------------------------
// Persistent GRU recurrence for one layer. 128 CTAs x 256 threads.
// CTA owns 8 state columns; U slices (3 x 1024 x 8) resident in SMEM.
// thread -> (c = tid&7, b = (tid>>3)&15, half = tid>>7); k-range 512 per half.
// ---------------------------------------------------------------------------
// Distributed-flag barrier: parallel arrivals (one flag per CTA), 128-thread
// poll. Flags reset to 0 by reset_kernel before each recur launch; gen is
// strictly increasing within a launch (1..512) so replays are safe.
__device__ __forceinline__ void grid_barrier(unsigned int gen) {
    __threadfence();
    __syncthreads();
    if (threadIdx.x == 0) g_flags[blockIdx.x] = gen;
    if (threadIdx.x < NB_RECUR) {
        while (g_flags[threadIdx.x] < gen) { }
    }
    __syncthreads();
}

#define RSTRIDE 1028                      // padded row stride (bank-conflict-free)
#define RECUR_SMEM ((3*8*RSTRIDE + 16*RSTRIDE + 3*128) * 4)

__global__ __launch_bounds__(256) void recur_kernel(
    const float* __restrict__ Gz, const float* __restrict__ Gr,
    const float* __restrict__ Gn,
    const float* __restrict__ Uz, const float* __restrict__ Ur,
    const float* __restrict__ Un,
    float* __restrict__ Hout, float* __restrict__ gh, float* __restrict__ grh)
{
    extern __shared__ float sm[];
    float* suz = sm;                       // [8][RSTRIDE]  (layout [c][k])
    float* sur = suz + 8 * RSTRIDE;
    float* sun = sur + 8 * RSTRIDE;
    float* shs = sun + 8 * RSTRIDE;        // [16][RSTRIDE] h / rh staging
    float* redz = shs + 16 * RSTRIDE;      // [128] partial sums from half=1
    float* redr = redz + 128;
    float* redn = redr + 128;

    int tid = threadIdx.x;
    int c0 = blockIdx.x * 8;

    // one-time weight preload (hidden-part slices, rows k, cols c0..c0+7)
    for (int i = tid; i < 8192; i += 256) {
        int k = i >> 3, c = i & 7;
        suz[c * RSTRIDE + k] = Uz[(size_t)k * SS + c0 + c];
        sur[c * RSTRIDE + k] = Ur[(size_t)k * SS + c0 + c];
        sun[c * RSTRIDE + k] = Un[(size_t)k * SS + c0 + c];
    }
    int c = tid & 7, b = (tid >> 3) & 15, half = tid >> 7;
    int k0 = half << 9;
    __syncthreads();

    const ulonglong2* hp = (const ulonglong2*)(shs + b * RSTRIDE + k0);
    const ulonglong2* zp = (const ulonglong2*)(suz + c * RSTRIDE + k0);
    const ulonglong2* rp = (const ulonglong2*)(sur + c * RSTRIDE + k0);
    const ulonglong2* np = (const ulonglong2*)(sun + c * RSTRIDE + k0);

    for (int t = 0; t < TT; t++) {
        // ---- stage h (L2, bypass stale L1) ----
        for (int i = tid * 4; i < BB * SS; i += 1024) {
            float4 v = __ldcg((const float4*)(gh + i));
            *(float4*)(shs + (i >> 10) * RSTRIDE + (i & 1023)) = v;
        }
        __syncthreads();

        ull az0 = 0, az1 = 0, ar0 = 0, ar1 = 0;
#pragma unroll 8
        for (int q = 0; q < 128; q++) {            // 512 k as 128x ulonglong2
            ulonglong2 h2 = hp[q];
            ulonglong2 z2 = zp[q];
            ulonglong2 r2 = rp[q];
            fma2(az0, h2.x, z2.x); fma2(az1, h2.y, z2.y);
            fma2(ar0, h2.x, r2.x); fma2(ar1, h2.y, r2.y);
        }
        float2 fz0 = u2f2(az0), fz1 = u2f2(az1);
        float2 fr0 = u2f2(ar0), fr1 = u2f2(ar1);
        float az = (fz0.x + fz0.y) + (fz1.x + fz1.y);
        float ar = (fr0.x + fr0.y) + (fr1.x + fr1.y);

        if (half) { redz[tid - 128] = az; redr[tid - 128] = ar; }
        __syncthreads();

        float zv = 0.f, hv = 0.f;
        if (!half) {
            int gcol = c0 + c;
            size_t grow = (size_t)(t * BB + b) * SS;
            float sz = az + redz[tid] + Gz[grow + gcol];
            float sr = ar + redr[tid] + Gr[grow + gcol];
            zv = 1.f / (1.f + expf(-sz));
            float rv = 1.f / (1.f + expf(-sr));
            hv = shs[b * RSTRIDE + gcol];
            grh[b * SS + gcol] = rv * hv;
        }
        grid_barrier(2 * t + 1);

        // ---- stage rh ----
        for (int i = tid * 4; i < BB * SS; i += 1024) {
            float4 v = __ldcg((const float4*)(grh + i));
            *(float4*)(shs + (i >> 10) * RSTRIDE + (i & 1023)) = v;
        }
        __syncthreads();

        ull an0 = 0, an1 = 0;
#pragma unroll 8
        for (int q = 0; q < 128; q++) {
            ulonglong2 h2 = hp[q];
            ulonglong2 n2 = np[q];
            fma2(an0, h2.x, n2.x); fma2(an1, h2.y, n2.y);
        }
        float2 fn0 = u2f2(an0), fn1 = u2f2(an1);
        float an = (fn0.x + fn0.y) + (fn1.x + fn1.y);

        if (half) redn[tid - 128] = an;
        __syncthreads();

        if (!half) {
            int gcol = c0 + c;
            size_t grow = (size_t)(t * BB + b) * SS;
            float nv = tanhf(an + redn[tid] + Gn[grow + gcol]);
            float hn = (1.f - zv) * hv + zv * nv;
            gh[b * SS + gcol] = hn;
            Hout[grow + gcol] = hn;
        }
        grid_barrier(2 * t + 2);
    }
}

// ---------------------------------------------------------------------------
extern "C" void kernel_launch(void* const* d_in, const int* in_sizes, int n_in,
                              void* d_out, int out_size) {
    const int*   x   = (const int*)  d_in[0];
    const float* emb = (const float*)d_in[1];
    const float* Wz  = (const float*)d_in[2];
    const float* bz  = (const float*)d_in[3];
    const float* Wr  = (const float*)d_in[4];
    const float* br  = (const float*)d_in[5];
    const float* Wn  = (const float*)d_in[6];
    const float* bn  = (const float*)d_in[7];
    const float* Wo  = (const float*)d_in[8];
    const float* bo  = (const float*)d_in[9];
    float* out = (float*)d_out;

    float* s = nullptr;
    cudaGetSymbolAddress((void**)&s, g_scratch);
    float* X0 = s;
    float* Gz = X0 + 4194304;
    float* Gr = Gz + 4194304;
    float* Gn = Gr + 4194304;
    float* H0 = Gn + 4194304;
    float* H1 = H0 + 4194304;
    float* gh = H1 + 4194304;
    float* grh = gh + 16384;

    cudaFuncSetAttribute(recur_kernel,
                         cudaFuncAttributeMaxDynamicSharedMemorySize, RECUR_SMEM);

    // Wz/Wr/Wn layout: [L][E+S][S]. Input part rows 0..1023; hidden rows 1024..2047.
    const size_t L0_IN  = 0;
    const size_t L0_HID = (size_t)1024 * 1024;
    const size_t L1_IN  = (size_t)2048 * 1024;
    const size_t L1_HID = (size_t)3072 * 1024;

    embed_kernel<<<MM, 256>>>(x, emb, X0);

    dim3 gg(SS / 128, MM / 128);     // gate GEMMs: N=1024
    // layer 0 input projections (bias folded in)
    gemm128<<<gg, 256>>>(X0, Wz + L0_IN, bz,      Gz, SS, SS, 0);
    gemm128<<<gg, 256>>>(X0, Wr + L0_IN, br,      Gr, SS, SS, 0);
    gemm128<<<gg, 256>>>(X0, Wn + L0_IN, bn,      Gn, SS, SS, 0);
    reset_kernel<<<64, 256>>>(gh);
    recur_kernel<<<NB_RECUR, 256, RECUR_SMEM>>>(Gz, Gr, Gn,
        Wz + L0_HID, Wr + L0_HID, Wn + L0_HID, H0, gh, grh);

    // layer 1 input projections from H0
    gemm128<<<gg, 256>>>(H0, Wz + L1_IN, bz + SS, Gz, SS, SS, 0);
    gemm128<<<gg, 256>>>(H0, Wr + L1_IN, br + SS, Gr, SS, SS, 0);
    gemm128<<<gg, 256>>>(H0, Wn + L1_IN, bn + SS, Gn, SS, SS, 0);
    reset_kernel<<<64, 256>>>(gh);
    recur_kernel<<<NB_RECUR, 256, RECUR_SMEM>>>(Gz, Gr, Gn,
        Wz + L1_HID, Wr + L1_HID, Wn + L1_HID, H1, gh, grh);

    // output projection with (t,b)->(b,t) remap
    dim3 go(VV / 128, MM / 128);
    gemm128<<<go, 256>>>(H1, Wo, bo, out, SS, VV, 1);

    if (out_size >= OUT_ELEMS + 2 * BB * SS)
        finalh_kernel<<<128, 256>>>(H0, H1, out + OUT_ELEMS);
}

// round 14
// speedup vs baseline: 1.6119x; 1.6119x over previous
#include <cuda_runtime.h>
#include <cuda_bf16.h>
#include <math.h>

#define BB 16
#define TT 256
#define SS 1024
#define VV 32000
#define MM (BB*TT)            // 4096 rows in the time-major stream
#define NB_RECUR 128
#define OUT_ELEMS 131072000   // B*T*V
#define KBIG 3072             // hi/lo-split K
#define NTILES (KBIG/32)      // 96 k-iterations

// ---------------- scratch (device globals; no runtime allocation) ----------
// fp32: X0,Gz,Gr,Gn,H0,H1 [4096*1024] each, gh/grh [16*1024]
__device__ __align__(256) float g_scratch[6 * 4194304 + 2 * 16384];
__device__ unsigned int g_bar_count;
__device__ unsigned int g_bar_gen;

// bf16: ABig [4096*3072], BWo [3072*32000], 6 gate B [3072*1024]
#define ABIG_ELEMS (4096*3072)
#define BWO_ELEMS  (3072*32000)
#define BG_ELEMS   (3072*1024)
__device__ __align__(256) __nv_bfloat16 g_bf[ABIG_ELEMS + BWO_ELEMS + 6 * BG_ELEMS];

// ---------------------------------------------------------------------------
__global__ void embed_kernel(const int* __restrict__ x,
                             const float* __restrict__ emb,
                             float* __restrict__ X0) {
    int row = blockIdx.x;              // row = t*16 + b
    int t = row >> 4, b = row & 15;
    int id = x[b * TT + t];            // x is [B, T]
    const float4* src = (const float4*)(emb + (size_t)id * SS);
    float4* dst = (float4*)(X0 + (size_t)row * SS);
    dst[threadIdx.x] = src[threadIdx.x];   // 256 thr * 4 = 1024
}

__global__ void zero_kernel(float* __restrict__ p, int n) {
    int i = blockIdx.x * blockDim.x + threadIdx.x;
    if (i < n) p[i] = 0.f;
}

// h_final[j][b][s] = Hj[(T-1)*16 + b][s]
__global__ void finalh_kernel(const float* __restrict__ H0,
                              const float* __restrict__ H1,
                              float* __restrict__ out) {
    int i = blockIdx.x * 256 + threadIdx.x;      // 0..32767
    const float* H = (i >> 14) ? H1 : H0;
    out[i] = H[(size_t)(TT - 1) * BB * SS + (i & 16383)];
}

// ---------------- hi/lo bf16 split conversions -----------------------------
// A: X [4096,1024] f32 -> Ab [4096,3072] bf16 as [hi | lo | hi]
__global__ void convA_kernel(const float* __restrict__ X,
                             __nv_bfloat16* __restrict__ Ab) {
    int i = (blockIdx.x * 256 + threadIdx.x) * 2;      // over 4096*1024
    int r = i >> 10, c = i & 1023;
    float2 v = *(const float2*)(X + i);
    __nv_bfloat16 h0 = __float2bfloat16(v.x);
    __nv_bfloat16 h1 = __float2bfloat16(v.y);
    __nv_bfloat16 l0 = __float2bfloat16(v.x - __bfloat162float(h0));
    __nv_bfloat16 l1 = __float2bfloat16(v.y - __bfloat162float(h1));
    __nv_bfloat162 hp; hp.x = h0; hp.y = h1;
    __nv_bfloat162 lp; lp.x = l0; lp.y = l1;
    size_t base = (size_t)r * KBIG + c;
    *(__nv_bfloat162*)(Ab + base)        = hp;
    *(__nv_bfloat162*)(Ab + base + 1024) = lp;
    *(__nv_bfloat162*)(Ab + base + 2048) = hp;
}

// B: W [1024,N] f32 (k rows, n cols) -> Bb [3072,N] bf16 as [hi ; hi ; lo]
__global__ void convB_kernel(const float* __restrict__ W,
                             __nv_bfloat16* __restrict__ Bb, int N) {
    long long i = ((long long)blockIdx.x * 256 + threadIdx.x) * 2;  // over 1024*N
    if (i >= (long long)1024 * N) return;
    int r = (int)(i / N), c = (int)(i % N);
    float2 v = *(const float2*)(W + i);
    __nv_bfloat16 h0 = __float2bfloat16(v.x);
    __nv_bfloat16 h1 = __float2bfloat16(v.y);
    __nv_bfloat16 l0 = __float2bfloat16(v.x - __bfloat162float(h0));
    __nv_bfloat16 l1 = __float2bfloat16(v.y - __bfloat162float(h1));
    __nv_bfloat162 hp; hp.x = h0; hp.y = h1;
    __nv_bfloat162 lp; lp.x = l0; lp.y = l1;
    size_t base = (size_t)r * N + c;
    *(__nv_bfloat162*)(Bb + base)                      = hp;
    *(__nv_bfloat162*)(Bb + base + (size_t)1024 * N)   = hp;
    *(__nv_bfloat162*)(Bb + base + (size_t)2048 * N)   = lp;
}

// ---------------- mma.sync bf16 GEMM ---------------------------------------
// C[M,N] = A[M,3072](bf16) @ B[3072,N](bf16) + bias[N], fp32 accum.
// CTA 128x128, BK=32, 256 thr, warp(4x2) -> 32x64 per warp (2x8 m16n8 tiles).
// remap!=0: output row m = t*16+b goes to row (b*T + t).
#define LDSM_X4(R, ADDR) \
    asm volatile("ldmatrix.sync.aligned.m8n8.x4.shared.b16 {%0,%1,%2,%3}, [%4];" \
        : "=r"((R)[0]), "=r"((R)[1]), "=r"((R)[2]), "=r"((R)[3]) : "r"(ADDR))
#define LDSM_X4T(R, ADDR) \
    asm volatile("ldmatrix.sync.aligned.m8n8.x4.trans.shared.b16 {%0,%1,%2,%3}, [%4];" \
        : "=r"((R)[0]), "=r"((R)[1]), "=r"((R)[2]), "=r"((R)[3]) : "r"(ADDR))
#define MMA16816(D, Ar, B0, B1) \
    asm volatile("mma.sync.aligned.m16n8k16.row.col.f32.bf16.bf16.f32 " \
        "{%0,%1,%2,%3}, {%4,%5,%6,%7}, {%8,%9}, {%0,%1,%2,%3};" \
        : "+f"((D)[0]), "+f"((D)[1]), "+f"((D)[2]), "+f"((D)[3]) \
        : "r"((Ar)[0]), "r"((Ar)[1]), "r"((Ar)[2]), "r"((Ar)[3]), \
          "r"(B0), "r"(B1))

#define APAD 40      // 32 + 8   (row stride 80B -> conflict-free LDSM)
#define BPAD 136     // 128 + 8  (row stride 272B -> conflict-free LDSM)
#define ATILE_B (128 * APAD * 2)
#define BTILE_B (32 * BPAD * 2)

__global__ __launch_bounds__(256) void gemm_bf16(
    const __nv_bfloat16* __restrict__ A, const __nv_bfloat16* __restrict__ Bm,
    const float* __restrict__ bias, float* __restrict__ C,
    int N, int remap)
{
    __shared__ __align__(16) __nv_bfloat16 As[2][128][APAD];
    __shared__ __align__(16) __nv_bfloat16 Bs[2][32][BPAD];

    int tid = threadIdx.x;
    int lane = tid & 31, wid = tid >> 5;
    int wm = wid & 3, wn = wid >> 2;
    int m0 = blockIdx.y * 128, n0 = blockIdx.x * 128;

    // global load mapping
    int ar0 = tid >> 2, ac0 = (tid & 3) * 8;          // + row 64 for 2nd
    int br0 = tid >> 4, bc0 = (tid & 15) * 8;         // + row 16 for 2nd
    const __nv_bfloat16* Ag  = A + (size_t)(m0 + ar0) * KBIG + ac0;
    const __nv_bfloat16* Ag2 = Ag + (size_t)64 * KBIG;
    const __nv_bfloat16* Bg  = Bm + (size_t)br0 * N + n0 + bc0;
    const __nv_bfloat16* Bg2 = Bg + (size_t)16 * N;

    // tile 0
    {
        int4 a0 = *(const int4*)Ag;
        int4 a1 = *(const int4*)Ag2;
        int4 b0 = *(const int4*)Bg;
        int4 b1 = *(const int4*)Bg2;
        *(int4*)&As[0][ar0][ac0]      = a0;
        *(int4*)&As[0][ar0 + 64][ac0] = a1;
        *(int4*)&Bs[0][br0][bc0]      = b0;
        *(int4*)&Bs[0][br0 + 16][bc0] = b1;
    }
    __syncthreads();

    // ldmatrix lane bases (bytes into shared window)
    unsigned sA = (unsigned)__cvta_generic_to_shared(&As[0][0][0]);
    unsigned sB = (unsigned)__cvta_generic_to_shared(&Bs[0][0][0]);
    unsigned aBase = sA + (unsigned)(((wm * 32 + (lane & 15)) * APAD + (lane >> 4) * 8) * 2);
    unsigned bBase = sB + (unsigned)(((lane & 15) * BPAD + wn * 64 + (lane >> 4) * 8) * 2);

    float acc[2][8][4];
#pragma unroll
    for (int i = 0; i < 2; i++)
#pragma unroll
        for (int j = 0; j < 8; j++)
#pragma unroll
            for (int q = 0; q < 4; q++) acc[i][j][q] = 0.f;

    int buf = 0;
    for (int kt = 0; kt < NTILES; kt++) {
        int4 pa0, pa1, pb0, pb1;
        if (kt + 1 < NTILES) {
            int ko = (kt + 1) * 32;
            pa0 = *(const int4*)(Ag + ko);
            pa1 = *(const int4*)(Ag2 + ko);
            pb0 = *(const int4*)(Bg + (size_t)ko * N);
            pb1 = *(const int4*)(Bg2 + (size_t)ko * N);
        }

        unsigned aB = aBase + buf * ATILE_B;
        unsigned bB = bBase + buf * BTILE_B;
#pragma unroll
        for (int k16 = 0; k16 < 2; k16++) {
            unsigned ra[2][4], rb[4][4];
            LDSM_X4(ra[0], aB + k16 * 32);
            LDSM_X4(ra[1], aB + k16 * 32 + 16 * APAD * 2);
            LDSM_X4T(rb[0], bB + k16 * (16 * BPAD * 2));
            LDSM_X4T(rb[1], bB + k16 * (16 * BPAD * 2) + 32);
            LDSM_X4T(rb[2], bB + k16 * (16 * BPAD * 2) + 64);
            LDSM_X4T(rb[3], bB + k16 * (16 * BPAD * 2) + 96);
#pragma unroll
            for (int mi = 0; mi < 2; mi++)
#pragma unroll
                for (int ni = 0; ni < 4; ni++) {
                    MMA16816(acc[mi][2 * ni],     ra[mi], rb[ni][0], rb[ni][1]);
                    MMA16816(acc[mi][2 * ni + 1], ra[mi], rb[ni][2], rb[ni][3]);
                }
        }

        if (kt + 1 < NTILES) {
            int nb = buf ^ 1;
            *(int4*)&As[nb][ar0][ac0]      = pa0;
            *(int4*)&As[nb][ar0 + 64][ac0] = pa1;
            *(int4*)&Bs[nb][br0][bc0]      = pb0;
            *(int4*)&Bs[nb][br0 + 16][bc0] = pb1;
            __syncthreads();
            buf = nb;
        }
    }

    // epilogue: bias + optional (t,b)->(b,t) remap; float2 per fragment row
#pragma unroll
    for (int mi = 0; mi < 2; mi++) {
        int m = m0 + wm * 32 + mi * 16 + (lane >> 2);
#pragma unroll
        for (int h8 = 0; h8 < 2; h8++) {
            int mm = m + h8 * 8;
            size_t orow = remap ? (size_t)((mm & 15) * TT + (mm >> 4)) * N
                                : (size_t)mm * N;
#pragma unroll
            for (int nj = 0; nj < 8; nj++) {
                int col = n0 + wn * 64 + nj * 8 + (lane & 3) * 2;
                float2 v;
                v.x = acc[mi][nj][h8 * 2 + 0] + bias[col];
                v.y = acc[mi][nj][h8 * 2 + 1] + bias[col + 1];
                *(float2*)(C + orow + col) = v;
            }
        }
    }
}

// ---------------------------------------------------------------------------
// Persistent GRU recurrence (R7-proven). 128 CTAs x 256 threads.
// ---------------------------------------------------------------------------
__device__ __forceinline__ void grid_barrier() {
    __threadfence();
    __syncthreads();
    if (threadIdx.x == 0) {
        unsigned int gen = *((volatile unsigned int*)&g_bar_gen);
        unsigned int a = atomicAdd(&g_bar_count, 1u);
        if (a == NB_RECUR - 1) {
            atomicExch(&g_bar_count, 0u);
            __threadfence();
            atomicAdd(&g_bar_gen, 1u);
        } else {
            while (*((volatile unsigned int*)&g_bar_gen) == gen) {}
        }
    }
    __syncthreads();
}

#define RSTRIDE 1028                      // padded row stride (bank-conflict-free)
#define RECUR_SMEM ((3*8*RSTRIDE + 16*RSTRIDE + 3*128) * 4)

__global__ __launch_bounds__(256) void recur_kernel(
    const float* __restrict__ Gz, const float* __restrict__ Gr,
    const float* __restrict__ Gn,
    const float* __restrict__ Uz, const float* __restrict__ Ur,
    const float* __restrict__ Un,
    float* __restrict__ Hout, float* __restrict__ gh, float* __restrict__ grh)
{
    extern __shared__ float sm[];
    float* suz = sm;                       // [8][RSTRIDE]  (layout [c][k])
    float* sur = suz + 8 * RSTRIDE;
    float* sun = sur + 8 * RSTRIDE;
    float* shs = sun + 8 * RSTRIDE;        // [16][RSTRIDE] h / rh staging
    float* redz = shs + 16 * RSTRIDE;      // [128] partial sums from half=1
    float* redr = redz + 128;
    float* redn = redr + 128;

    int tid = threadIdx.x;
    int c0 = blockIdx.x * 8;

    for (int i = tid; i < 8192; i += 256) {
        int k = i >> 3, c = i & 7;
        suz[c * RSTRIDE + k] = Uz[(size_t)k * SS + c0 + c];
        sur[c * RSTRIDE + k] = Ur[(size_t)k * SS + c0 + c];
        sun[c * RSTRIDE + k] = Un[(size_t)k * SS + c0 + c];
    }
    int c = tid & 7, b = (tid >> 3) & 15, half = tid >> 7;
    int k0 = half << 9;
    __syncthreads();

    for (int t = 0; t < TT; t++) {
        for (int i = tid * 4; i < BB * SS; i += 1024) {
            float4 v = __ldcg((const float4*)(gh + i));
            *(float4*)(shs + (i >> 10) * RSTRIDE + (i & 1023)) = v;
        }
        __syncthreads();

        const float* hr  = shs + b * RSTRIDE + k0;
        const float* uzc = suz + c * RSTRIDE + k0;
        const float* urc = sur + c * RSTRIDE + k0;
        float az = 0.f, ar = 0.f;
#pragma unroll 8
        for (int k = 0; k < 512; k += 4) {
            float4 h4 = *(const float4*)(hr + k);
            float4 z4 = *(const float4*)(uzc + k);
            float4 r4 = *(const float4*)(urc + k);
            az = fmaf(h4.x, z4.x, az); az = fmaf(h4.y, z4.y, az);
            az = fmaf(h4.z, z4.z, az); az = fmaf(h4.w, z4.w, az);
            ar = fmaf(h4.x, r4.x, ar); ar = fmaf(h4.y, r4.y, ar);
            ar = fmaf(h4.z, r4.z, ar); ar = fmaf(h4.w, r4.w, ar);
        }
        if (half) { redz[tid - 128] = az; redr[tid - 128] = ar; }
        __syncthreads();

        float zv = 0.f, hv = 0.f;
        if (!half) {
            int gcol = c0 + c;
            size_t grow = (size_t)(t * BB + b) * SS;
            float sz = az + redz[tid] + Gz[grow + gcol];
            float sr = ar + redr[tid] + Gr[grow + gcol];
            zv = 1.f / (1.f + expf(-sz));
            float rv = 1.f / (1.f + expf(-sr));
            hv = shs[b * RSTRIDE + gcol];
            grh[b * SS + gcol] = rv * hv;
        }
        grid_barrier();

        for (int i = tid * 4; i < BB * SS; i += 1024) {
            float4 v = __ldcg((const float4*)(grh + i));
            *(float4*)(shs + (i >> 10) * RSTRIDE + (i & 1023)) = v;
        }
        __syncthreads();

        const float* unc = sun + c * RSTRIDE + k0;
        float an = 0.f;
#pragma unroll 8
        for (int k = 0; k < 512; k += 4) {
            float4 h4 = *(const float4*)(hr + k);
            float4 n4 = *(const float4*)(unc + k);
            an = fmaf(h4.x, n4.x, an); an = fmaf(h4.y, n4.y, an);
            an = fmaf(h4.z, n4.z, an); an = fmaf(h4.w, n4.w, an);
        }
        if (half) redn[tid - 128] = an;
        __syncthreads();

        if (!half) {
            int gcol = c0 + c;
            size_t grow = (size_t)(t * BB + b) * SS;
            float nv = tanhf(an + redn[tid] + Gn[grow + gcol]);
            float hn = (1.f - zv) * hv + zv * nv;
            gh[b * SS + gcol] = hn;
            Hout[grow + gcol] = hn;
        }
        grid_barrier();
    }
}

// ---------------------------------------------------------------------------
extern "C" void kernel_launch(void* const* d_in, const int* in_sizes, int n_in,
                              void* d_out, int out_size) {
    const int*   x   = (const int*)  d_in[0];
    const float* emb = (const float*)d_in[1];
    const float* Wz  = (const float*)d_in[2];
    const float* bz  = (const float*)d_in[3];
    const float* Wr  = (const float*)d_in[4];
    const float* br  = (const float*)d_in[5];
    const float* Wn  = (const float*)d_in[6];
    const float* bn  = (const float*)d_in[7];
    const float* Wo  = (const float*)d_in[8];
    const float* bo  = (const float*)d_in[9];
    float* out = (float*)d_out;

    float* s = nullptr;
    cudaGetSymbolAddress((void**)&s, g_scratch);
    float* X0 = s;
    float* Gz = X0 + 4194304;
    float* Gr = Gz + 4194304;
    float* Gn = Gr + 4194304;
    float* H0 = Gn + 4194304;
    float* H1 = H0 + 4194304;
    float* gh = H1 + 4194304;
    float* grh = gh + 16384;

    __nv_bfloat16* bf = nullptr;
    cudaGetSymbolAddress((void**)&bf, g_bf);
    __nv_bfloat16* Ab  = bf;
    __nv_bfloat16* bWo = Ab + ABIG_ELEMS;
    __nv_bfloat16* bG[6];
    for (int g = 0; g < 6; g++) bG[g] = bWo + BWO_ELEMS + (size_t)g * BG_ELEMS;

    cudaFuncSetAttribute(recur_kernel,
                         cudaFuncAttributeMaxDynamicSharedMemorySize, RECUR_SMEM);

    // Wz/Wr/Wn layout: [L][E+S][S]. Input rows 0..1023; hidden rows 1024..2047.
    const size_t L0_IN  = 0;
    const size_t L0_HID = (size_t)1024 * 1024;
    const size_t L1_IN  = (size_t)2048 * 1024;
    const size_t L1_HID = (size_t)3072 * 1024;

    // weight conversions (hi/lo split, every call — no caching)
    const int gbGate = (1024 * 1024 / 2 + 255) / 256;          // 2048
    convB_kernel<<<gbGate, 256>>>(Wz + L0_IN, bG[0], SS);
    convB_kernel<<<gbGate, 256>>>(Wr + L0_IN, bG[1], SS);
    convB_kernel<<<gbGate, 256>>>(Wn + L0_IN, bG[2], SS);
    convB_kernel<<<gbGate, 256>>>(Wz + L1_IN, bG[3], SS);
    convB_kernel<<<gbGate, 256>>>(Wr + L1_IN, bG[4], SS);
    convB_kernel<<<gbGate, 256>>>(Wn + L1_IN, bG[5], SS);
    const long long woElems = (long long)1024 * VV;
    convB_kernel<<<(unsigned)((woElems / 2 + 255) / 256), 256>>>(Wo, bWo, VV);

    embed_kernel<<<MM, 256>>>(x, emb, X0);

    const int gbA = MM * SS / 2 / 256;                          // 8192
    dim3 gg(SS / 128, MM / 128);                                // (8, 32)

    // layer 0
    convA_kernel<<<gbA, 256>>>(X0, Ab);
    gemm_bf16<<<gg, 256>>>(Ab, bG[0], bz,      Gz, SS, 0);
    gemm_bf16<<<gg, 256>>>(Ab, bG[1], br,      Gr, SS, 0);
    gemm_bf16<<<gg, 256>>>(Ab, bG[2], bn,      Gn, SS, 0);
    zero_kernel<<<64, 256>>>(gh, BB * SS);
    recur_kernel<<<NB_RECUR, 256, RECUR_SMEM>>>(Gz, Gr, Gn,
        Wz + L0_HID, Wr + L0_HID, Wn + L0_HID, H0, gh, grh);

    // layer 1
    convA_kernel<<<gbA, 256>>>(H0, Ab);
    gemm_bf16<<<gg, 256>>>(Ab, bG[3], bz + SS, Gz, SS, 0);
    gemm_bf16<<<gg, 256>>>(Ab, bG[4], br + SS, Gr, SS, 0);
    gemm_bf16<<<gg, 256>>>(Ab, bG[5], bn + SS, Gn, SS, 0);
    zero_kernel<<<64, 256>>>(gh, BB * SS);
    recur_kernel<<<NB_RECUR, 256, RECUR_SMEM>>>(Gz, Gr, Gn,
        Wz + L1_HID, Wr + L1_HID, Wn + L1_HID, H1, gh, grh);

    // output projection with (t,b)->(b,t) remap
    convA_kernel<<<gbA, 256>>>(H1, Ab);
    dim3 go(VV / 128, MM / 128);                                // (250, 32)
    gemm_bf16<<<go, 256>>>(Ab, bWo, bo, out, VV, 1);

    if (out_size >= OUT_ELEMS + 2 * BB * SS)
        finalh_kernel<<<128, 256>>>(H0, H1, out + OUT_ELEMS);
}

// round 16
// speedup vs baseline: 1.9309x; 1.1979x over previous
#include <cuda_runtime.h>
#include <cuda_bf16.h>
#include <math.h>

#define BB 16
#define TT 256
#define SS 1024
#define VV 32000
#define MM (BB*TT)            // 4096 rows in the time-major stream
#define NB_RECUR 128
#define OUT_ELEMS 131072000   // B*T*V
#define KBIG 3072             // hi/lo-split K
#define NTILES (KBIG/32)      // 96 k-iterations

// ---------------- scratch (device globals; no runtime allocation) ----------
// fp32: X0,Gz,Gr,Gn,H0,H1 [4096*1024] each, gh/grh [16*1024]
__device__ __align__(256) float g_scratch[6 * 4194304 + 2 * 16384];
__device__ unsigned int g_bar_grp[16 * 32];   // group counters, 128B apart
__device__ unsigned int g_bar_count;
__device__ unsigned int g_bar_gen;

// bf16: ABig [4096*3072], BWo [3072*32000], 6 gate B [3072*1024]
#define ABIG_ELEMS (4096*3072)
#define BWO_ELEMS  (3072*32000)
#define BG_ELEMS   (3072*1024)
__device__ __align__(256) __nv_bfloat16 g_bf[ABIG_ELEMS + BWO_ELEMS + 6 * BG_ELEMS];

// ---------------------------------------------------------------------------
__global__ void embed_kernel(const int* __restrict__ x,
                             const float* __restrict__ emb,
                             float* __restrict__ X0) {
    int row = blockIdx.x;              // row = t*16 + b
    int t = row >> 4, b = row & 15;
    int id = x[b * TT + t];            // x is [B, T]
    const float4* src = (const float4*)(emb + (size_t)id * SS);
    float4* dst = (float4*)(X0 + (size_t)row * SS);
    dst[threadIdx.x] = src[threadIdx.x];   // 256 thr * 4 = 1024
}

__global__ void zero_kernel(float* __restrict__ p, int n) {
    int i = blockIdx.x * blockDim.x + threadIdx.x;
    if (i < n) p[i] = 0.f;
}

// h_final[j][b][s] = Hj[(T-1)*16 + b][s]
__global__ void finalh_kernel(const float* __restrict__ H0,
                              const float* __restrict__ H1,
                              float* __restrict__ out) {
    int i = blockIdx.x * 256 + threadIdx.x;      // 0..32767
    const float* H = (i >> 14) ? H1 : H0;
    out[i] = H[(size_t)(TT - 1) * BB * SS + (i & 16383)];
}

// ---------------- hi/lo bf16 split conversions -----------------------------
// A: X [4096,1024] f32 -> Ab [4096,3072] bf16 as [hi | lo | hi]
__global__ void convA_kernel(const float* __restrict__ X,
                             __nv_bfloat16* __restrict__ Ab) {
    int i = (blockIdx.x * 256 + threadIdx.x) * 2;      // over 4096*1024
    int r = i >> 10, c = i & 1023;
    float2 v = *(const float2*)(X + i);
    __nv_bfloat16 h0 = __float2bfloat16(v.x);
    __nv_bfloat16 h1 = __float2bfloat16(v.y);
    __nv_bfloat16 l0 = __float2bfloat16(v.x - __bfloat162float(h0));
    __nv_bfloat16 l1 = __float2bfloat16(v.y - __bfloat162float(h1));
    __nv_bfloat162 hp; hp.x = h0; hp.y = h1;
    __nv_bfloat162 lp; lp.x = l0; lp.y = l1;
    size_t base = (size_t)r * KBIG + c;
    *(__nv_bfloat162*)(Ab + base)        = hp;
    *(__nv_bfloat162*)(Ab + base + 1024) = lp;
    *(__nv_bfloat162*)(Ab + base + 2048) = hp;
}

// B: W [1024,N] f32 (k rows, n cols) -> Bb [3072,N] bf16 as [hi ; hi ; lo]
__global__ void convB_kernel(const float* __restrict__ W,
                             __nv_bfloat16* __restrict__ Bb, int N) {
    long long i = ((long long)blockIdx.x * 256 + threadIdx.x) * 2;  // over 1024*N
    if (i >= (long long)1024 * N) return;
    int r = (int)(i / N), c = (int)(i % N);
    float2 v = *(const float2*)(W + i);
    __nv_bfloat16 h0 = __float2bfloat16(v.x);
    __nv_bfloat16 h1 = __float2bfloat16(v.y);
    __nv_bfloat16 l0 = __float2bfloat16(v.x - __bfloat162float(h0));
    __nv_bfloat16 l1 = __float2bfloat16(v.y - __bfloat162float(h1));
    __nv_bfloat162 hp; hp.x = h0; hp.y = h1;
    __nv_bfloat162 lp; lp.x = l0; lp.y = l1;
    size_t base = (size_t)r * N + c;
    *(__nv_bfloat162*)(Bb + base)                      = hp;
    *(__nv_bfloat162*)(Bb + base + (size_t)1024 * N)   = hp;
    *(__nv_bfloat162*)(Bb + base + (size_t)2048 * N)   = lp;
}

// ---------------- mma.sync bf16 GEMM (cp.async 4-stage) --------------------
// C[M,N] = A[M,3072](bf16) @ B[3072,N](bf16) + bias[N], fp32 accum.
// CTA 128x128, BK=32, 256 thr, warp(4x2) -> 32x64 per warp (2x8 m16n8 tiles).
// remap!=0: output row m = t*16+b goes to row (b*T + t).
#define LDSM_X4(R, ADDR) \
    asm volatile("ldmatrix.sync.aligned.m8n8.x4.shared.b16 {%0,%1,%2,%3}, [%4];" \
        : "=r"((R)[0]), "=r"((R)[1]), "=r"((R)[2]), "=r"((R)[3]) : "r"(ADDR))
#define LDSM_X4T(R, ADDR) \
    asm volatile("ldmatrix.sync.aligned.m8n8.x4.trans.shared.b16 {%0,%1,%2,%3}, [%4];" \
        : "=r"((R)[0]), "=r"((R)[1]), "=r"((R)[2]), "=r"((R)[3]) : "r"(ADDR))
#define MMA16816(D, Ar, B0, B1) \
    asm volatile("mma.sync.aligned.m16n8k16.row.col.f32.bf16.bf16.f32 " \
        "{%0,%1,%2,%3}, {%4,%5,%6,%7}, {%8,%9}, {%0,%1,%2,%3};" \
        : "+f"((D)[0]), "+f"((D)[1]), "+f"((D)[2]), "+f"((D)[3]) \
        : "r"((Ar)[0]), "r"((Ar)[1]), "r"((Ar)[2]), "r"((Ar)[3]), \
          "r"(B0), "r"(B1))

__device__ __forceinline__ void cpa16(unsigned dst, const void* src) {
    asm volatile("cp.async.ca.shared.global [%0], [%1], 16;" :: "r"(dst), "l"(src));
}
#define CP_COMMIT() asm volatile("cp.async.commit_group;")
#define CP_WAIT2()  asm volatile("cp.async.wait_group 2;")

#define APAD 40      // 32 + 8   (row stride 80B -> conflict-free LDSM)
#define BPAD 136     // 128 + 8  (row stride 272B -> conflict-free LDSM)
#define ATILE_B (128 * APAD * 2)
#define BTILE_B (32 * BPAD * 2)
#define NSTAGE 4

__global__ __launch_bounds__(256) void gemm_bf16(
    const __nv_bfloat16* __restrict__ A, const __nv_bfloat16* __restrict__ Bm,
    const float* __restrict__ bias, float* __restrict__ C,
    int N, int remap)
{
    __shared__ __align__(16) __nv_bfloat16 As[NSTAGE][128][APAD];
    __shared__ __align__(16) __nv_bfloat16 Bs[NSTAGE][32][BPAD];

    int tid = threadIdx.x;
    int lane = tid & 31, wid = tid >> 5;
    int wm = wid & 3, wn = wid >> 2;
    int m0 = blockIdx.y * 128, n0 = blockIdx.x * 128;

    // global load mapping
    int ar0 = tid >> 2, ac0 = (tid & 3) * 8;          // + row 64 for 2nd
    int br0 = tid >> 4, bc0 = (tid & 15) * 8;         // + row 16 for 2nd
    const __nv_bfloat16* Ag  = A + (size_t)(m0 + ar0) * KBIG + ac0;
    const __nv_bfloat16* Ag2 = Ag + (size_t)64 * KBIG;
    const __nv_bfloat16* Bg  = Bm + (size_t)br0 * N + n0 + bc0;
    const __nv_bfloat16* Bg2 = Bg + (size_t)16 * N;

    unsigned sA = (unsigned)__cvta_generic_to_shared(&As[0][0][0]);
    unsigned sB = (unsigned)__cvta_generic_to_shared(&Bs[0][0][0]);
    unsigned aDst  = sA + (unsigned)((ar0 * APAD + ac0) * 2);
    unsigned aDst2 = sA + (unsigned)(((ar0 + 64) * APAD + ac0) * 2);
    unsigned bDst  = sB + (unsigned)((br0 * BPAD + bc0) * 2);
    unsigned bDst2 = sB + (unsigned)(((br0 + 16) * BPAD + bc0) * 2);

    // prologue: issue 3 stages
#pragma unroll
    for (int s = 0; s < NSTAGE - 1; s++) {
        int ko = s * 32;
        cpa16(aDst  + s * ATILE_B, Ag  + ko);
        cpa16(aDst2 + s * ATILE_B, Ag2 + ko);
        cpa16(bDst  + s * BTILE_B, Bg  + (size_t)ko * N);
        cpa16(bDst2 + s * BTILE_B, Bg2 + (size_t)ko * N);
        CP_COMMIT();
    }

    // ldmatrix lane bases
    unsigned aBase = sA + (unsigned)(((wm * 32 + (lane & 15)) * APAD + (lane >> 4) * 8) * 2);
    unsigned bBase = sB + (unsigned)(((lane & 15) * BPAD + wn * 64 + (lane >> 4) * 8) * 2);

    float acc[2][8][4];
#pragma unroll
    for (int i = 0; i < 2; i++)
#pragma unroll
        for (int j = 0; j < 8; j++)
#pragma unroll
            for (int q = 0; q < 4; q++) acc[i][j][q] = 0.f;

    for (int kt = 0; kt < NTILES; kt++) {
        CP_WAIT2();
        __syncthreads();

        // issue stage kt+3 (overwrites buffer of stage kt-1; all warps are
        // past compute(kt-1) because they passed the barrier above)
        if (kt + NSTAGE - 1 < NTILES) {
            int s = (kt + NSTAGE - 1) & (NSTAGE - 1);
            int ko = (kt + NSTAGE - 1) * 32;
            cpa16(aDst  + s * ATILE_B, Ag  + ko);
            cpa16(aDst2 + s * ATILE_B, Ag2 + ko);
            cpa16(bDst  + s * BTILE_B, Bg  + (size_t)ko * N);
            cpa16(bDst2 + s * BTILE_B, Bg2 + (size_t)ko * N);
            CP_COMMIT();
        }

        int buf = kt & (NSTAGE - 1);
        unsigned aB = aBase + buf * ATILE_B;
        unsigned bB = bBase + buf * BTILE_B;
#pragma unroll
        for (int k16 = 0; k16 < 2; k16++) {
            unsigned ra[2][4], rb[4][4];
            LDSM_X4(ra[0], aB + k16 * 32);
            LDSM_X4(ra[1], aB + k16 * 32 + 16 * APAD * 2);
            LDSM_X4T(rb[0], bB + k16 * (16 * BPAD * 2));
            LDSM_X4T(rb[1], bB + k16 * (16 * BPAD * 2) + 32);
            LDSM_X4T(rb[2], bB + k16 * (16 * BPAD * 2) + 64);
            LDSM_X4T(rb[3], bB + k16 * (16 * BPAD * 2) + 96);
#pragma unroll
            for (int mi = 0; mi < 2; mi++)
#pragma unroll
                for (int ni = 0; ni < 4; ni++) {
                    MMA16816(acc[mi][2 * ni],     ra[mi], rb[ni][0], rb[ni][1]);
                    MMA16816(acc[mi][2 * ni + 1], ra[mi], rb[ni][2], rb[ni][3]);
                }
        }
    }

    // epilogue: bias + optional (t,b)->(b,t) remap; float2 per fragment row
#pragma unroll
    for (int mi = 0; mi < 2; mi++) {
        int m = m0 + wm * 32 + mi * 16 + (lane >> 2);
#pragma unroll
        for (int h8 = 0; h8 < 2; h8++) {
            int mm = m + h8 * 8;
            size_t orow = remap ? (size_t)((mm & 15) * TT + (mm >> 4)) * N
                                : (size_t)mm * N;
#pragma unroll
            for (int nj = 0; nj < 8; nj++) {
                int col = n0 + wn * 64 + nj * 8 + (lane & 3) * 2;
                float2 v;
                v.x = acc[mi][nj][h8 * 2 + 0] + bias[col];
                v.y = acc[mi][nj][h8 * 2 + 1] + bias[col + 1];
                *(float2*)(C + orow + col) = v;
            }
        }
    }
}

// ---------------------------------------------------------------------------
// Persistent GRU recurrence. 128 CTAs x 256 threads.
// Hierarchical barrier: 16 groups x 8 CTAs; group counters on distinct 128B
// lines (distinct LTS slices); single-address gen poll (R7-proven).
// Counters return to 0 after each use -> graph-replay safe.
// ---------------------------------------------------------------------------
__device__ __forceinline__ void grid_barrier() {
    __threadfence();
    __syncthreads();
    if (threadIdx.x == 0) {
        unsigned int gen = *((volatile unsigned int*)&g_bar_gen);
        int grp = (blockIdx.x >> 3) * 32;
        if (atomicAdd(&g_bar_grp[grp], 1u) == 7u) {
            atomicExch(&g_bar_grp[grp], 0u);
            if (atomicAdd(&g_bar_count, 1u) == 15u) {
                atomicExch(&g_bar_count, 0u);
                __threadfence();
                atomicAdd(&g_bar_gen, 1u);
            }
        }
        while (*((volatile unsigned int*)&g_bar_gen) == gen) {}
    }
    __syncthreads();
}

#define RSTRIDE 1028                      // padded row stride (bank-conflict-free)
#define RECUR_SMEM ((3*8*RSTRIDE + 16*RSTRIDE + 3*128) * 4)

__global__ __launch_bounds__(256) void recur_kernel(
    const float* __restrict__ Gz, const float* __restrict__ Gr,
    const float* __restrict__ Gn,
    const float* __restrict__ Uz, const float* __restrict__ Ur,
    const float* __restrict__ Un,
    float* __restrict__ Hout, float* __restrict__ gh, float* __restrict__ grh)
{
    extern __shared__ float sm[];
    float* suz = sm;                       // [8][RSTRIDE]  (layout [c][k])
    float* sur = suz + 8 * RSTRIDE;
    float* sun = sur + 8 * RSTRIDE;
    float* shs = sun + 8 * RSTRIDE;        // [16][RSTRIDE] h / rh staging
    float* redz = shs + 16 * RSTRIDE;      // [128] partial sums from half=1
    float* redr = redz + 128;
    float* redn = redr + 128;

    int tid = threadIdx.x;
    int c0 = blockIdx.x * 8;

    for (int i = tid; i < 8192; i += 256) {
        int k = i >> 3, c = i & 7;
        suz[c * RSTRIDE + k] = Uz[(size_t)k * SS + c0 + c];
        sur[c * RSTRIDE + k] = Ur[(size_t)k * SS + c0 + c];
        sun[c * RSTRIDE + k] = Un[(size_t)k * SS + c0 + c];
    }
    int c = tid & 7, b = (tid >> 3) & 15, half = tid >> 7;
    int k0 = half << 9;
    __syncthreads();

    for (int t = 0; t < TT; t++) {
        for (int i = tid * 4; i < BB * SS; i += 1024) {
            float4 v = __ldcg((const float4*)(gh + i));
            *(float4*)(shs + (i >> 10) * RSTRIDE + (i & 1023)) = v;
        }
        __syncthreads();

        const float* hr  = shs + b * RSTRIDE + k0;
        const float* uzc = suz + c * RSTRIDE + k0;
        const float* urc = sur + c * RSTRIDE + k0;
        float az = 0.f, ar = 0.f;
#pragma unroll 8
        for (int k = 0; k < 512; k += 4) {
            float4 h4 = *(const float4*)(hr + k);
            float4 z4 = *(const float4*)(uzc + k);
            float4 r4 = *(const float4*)(urc + k);
            az = fmaf(h4.x, z4.x, az); az = fmaf(h4.y, z4.y, az);
            az = fmaf(h4.z, z4.z, az); az = fmaf(h4.w, z4.w, az);
            ar = fmaf(h4.x, r4.x, ar); ar = fmaf(h4.y, r4.y, ar);
            ar = fmaf(h4.z, r4.z, ar); ar = fmaf(h4.w, r4.w, ar);
        }
        if (half) { redz[tid - 128] = az; redr[tid - 128] = ar; }
        __syncthreads();

        float zv = 0.f, hv = 0.f;
        if (!half) {
            int gcol = c0 + c;
            size_t grow = (size_t)(t * BB + b) * SS;
            float sz = az + redz[tid] + Gz[grow + gcol];
            float sr = ar + redr[tid] + Gr[grow + gcol];
            zv = 1.f / (1.f + expf(-sz));
            float rv = 1.f / (1.f + expf(-sr));
            hv = shs[b * RSTRIDE + gcol];
            grh[b * SS + gcol] = rv * hv;
        }
        grid_barrier();

        for (int i = tid * 4; i < BB * SS; i += 1024) {
            float4 v = __ldcg((const float4*)(grh + i));
            *(float4*)(shs + (i >> 10) * RSTRIDE + (i & 1023)) = v;
        }
        __syncthreads();

        const float* unc = sun + c * RSTRIDE + k0;
        float an = 0.f;
#pragma unroll 8
        for (int k = 0; k < 512; k += 4) {
            float4 h4 = *(const float4*)(hr + k);
            float4 n4 = *(const float4*)(unc + k);
            an = fmaf(h4.x, n4.x, an); an = fmaf(h4.y, n4.y, an);
            an = fmaf(h4.z, n4.z, an); an = fmaf(h4.w, n4.w, an);
        }
        if (half) redn[tid - 128] = an;
        __syncthreads();

        if (!half) {
            int gcol = c0 + c;
            size_t grow = (size_t)(t * BB + b) * SS;
            float nv = tanhf(an + redn[tid] + Gn[grow + gcol]);
            float hn = (1.f - zv) * hv + zv * nv;
            gh[b * SS + gcol] = hn;
            Hout[grow + gcol] = hn;
        }
        grid_barrier();
    }
}

// ---------------------------------------------------------------------------
extern "C" void kernel_launch(void* const* d_in, const int* in_sizes, int n_in,
                              void* d_out, int out_size) {
    const int*   x   = (const int*)  d_in[0];
    const float* emb = (const float*)d_in[1];
    const float* Wz  = (const float*)d_in[2];
    const float* bz  = (const float*)d_in[3];
    const float* Wr  = (const float*)d_in[4];
    const float* br  = (const float*)d_in[5];
    const float* Wn  = (const float*)d_in[6];
    const float* bn  = (const float*)d_in[7];
    const float* Wo  = (const float*)d_in[8];
    const float* bo  = (const float*)d_in[9];
    float* out = (float*)d_out;

    float* s = nullptr;
    cudaGetSymbolAddress((void**)&s, g_scratch);
    float* X0 = s;
    float* Gz = X0 + 4194304;
    float* Gr = Gz + 4194304;
    float* Gn = Gr + 4194304;
    float* H0 = Gn + 4194304;
    float* H1 = H0 + 4194304;
    float* gh = H1 + 4194304;
    float* grh = gh + 16384;

    __nv_bfloat16* bf = nullptr;
    cudaGetSymbolAddress((void**)&bf, g_bf);
    __nv_bfloat16* Ab  = bf;
    __nv_bfloat16* bWo = Ab + ABIG_ELEMS;
    __nv_bfloat16* bG[6];
    for (int g = 0; g < 6; g++) bG[g] = bWo + BWO_ELEMS + (size_t)g * BG_ELEMS;

    cudaFuncSetAttribute(recur_kernel,
                         cudaFuncAttributeMaxDynamicSharedMemorySize, RECUR_SMEM);

    // Wz/Wr/Wn layout: [L][E+S][S]. Input rows 0..1023; hidden rows 1024..2047.
    const size_t L0_IN  = 0;
    const size_t L0_HID = (size_t)1024 * 1024;
    const size_t L1_IN  = (size_t)2048 * 1024;
    const size_t L1_HID = (size_t)3072 * 1024;

    // weight conversions (hi/lo split, every call — no caching)
    const int gbGate = (1024 * 1024 / 2 + 255) / 256;          // 2048
    convB_kernel<<<gbGate, 256>>>(Wz + L0_IN, bG[0], SS);
    convB_kernel<<<gbGate, 256>>>(Wr + L0_IN, bG[1], SS);
    convB_kernel<<<gbGate, 256>>>(Wn + L0_IN, bG[2], SS);
    convB_kernel<<<gbGate, 256>>>(Wz + L1_IN, bG[3], SS);
    convB_kernel<<<gbGate, 256>>>(Wr + L1_IN, bG[4], SS);
    convB_kernel<<<gbGate, 256>>>(Wn + L1_IN, bG[5], SS);
    const long long woElems = (long long)1024 * VV;
    convB_kernel<<<(unsigned)((woElems / 2 + 255) / 256), 256>>>(Wo, bWo, VV);

    embed_kernel<<<MM, 256>>>(x, emb, X0);

    const int gbA = MM * SS / 2 / 256;                          // 8192
    dim3 gg(SS / 128, MM / 128);                                // (8, 32)

    // layer 0
    convA_kernel<<<gbA, 256>>>(X0, Ab);
    gemm_bf16<<<gg, 256>>>(Ab, bG[0], bz,      Gz, SS, 0);
    gemm_bf16<<<gg, 256>>>(Ab, bG[1], br,      Gr, SS, 0);
    gemm_bf16<<<gg, 256>>>(Ab, bG[2], bn,      Gn, SS, 0);
    zero_kernel<<<64, 256>>>(gh, BB * SS);
    recur_kernel<<<NB_RECUR, 256, RECUR_SMEM>>>(Gz, Gr, Gn,
        Wz + L0_HID, Wr + L0_HID, Wn + L0_HID, H0, gh, grh);

    // layer 1
    convA_kernel<<<gbA, 256>>>(H0, Ab);
    gemm_bf16<<<gg, 256>>>(Ab, bG[3], bz + SS, Gz, SS, 0);
    gemm_bf16<<<gg, 256>>>(Ab, bG[4], br + SS, Gr, SS, 0);
    gemm_bf16<<<gg, 256>>>(Ab, bG[5], bn + SS, Gn, SS, 0);
    zero_kernel<<<64, 256>>>(gh, BB * SS);
    recur_kernel<<<NB_RECUR, 256, RECUR_SMEM>>>(Gz, Gr, Gn,
        Wz + L1_HID, Wr + L1_HID, Wn + L1_HID, H1, gh, grh);

    // output projection with (t,b)->(b,t) remap
    convA_kernel<<<gbA, 256>>>(H1, Ab);
    dim3 go(VV / 128, MM / 128);                                // (250, 32)
    gemm_bf16<<<go, 256>>>(Ab, bWo, bo, out, VV, 1);

    if (out_size >= OUT_ELEMS + 2 * BB * SS)
        finalh_kernel<<<128, 256>>>(H0, H1, out + OUT_ELEMS);
}

// round 17
// speedup vs baseline: 2.7016x; 1.3991x over previous
#include <cuda_runtime.h>
#include <cuda_bf16.h>
#include <math.h>

#define BB 16
#define TT 256
#define SS 1024
#define VV 32000
#define MM (BB*TT)            // 4096 rows in the time-major stream
#define NB_RECUR 128
#define OUT_ELEMS 131072000   // B*T*V
#define KBIG 3072             // hi/lo-split K
#define NTILES (KBIG/32)      // 96 k-iterations

// ---------------- scratch (device globals; no runtime allocation) ----------
// fp32: X0,Gz,Gr,Gn,H0,H1 [4096*1024] each
__device__ __align__(256) float g_scratch[6 * 4194304 + 2 * 16384];
__device__ unsigned int g_bar_grp[16 * 32];   // group counters, 128B apart
__device__ unsigned int g_bar_count;
__device__ unsigned int g_bar_gen;

// bf16: ABig [4096*3072], BWo [3072*32000], 6 gate B [3072*1024]
#define ABIG_ELEMS (4096*3072)
#define BWO_ELEMS  (3072*32000)
#define BG_ELEMS   (3072*1024)
__device__ __align__(256) __nv_bfloat16 g_bf[ABIG_ELEMS + BWO_ELEMS + 6 * BG_ELEMS];
// recurrent state published as bf16 hi/lo: [16][2048] = [hi(1024)|lo(1024)]
__device__ __align__(256) __nv_bfloat16 g_hbf[16 * 2048];
__device__ __align__(256) __nv_bfloat16 g_rhbf[16 * 2048];

// ---------------------------------------------------------------------------
__global__ void embed_kernel(const int* __restrict__ x,
                             const float* __restrict__ emb,
                             float* __restrict__ X0) {
    int row = blockIdx.x;              // row = t*16 + b
    int t = row >> 4, b = row & 15;
    int id = x[b * TT + t];            // x is [B, T]
    const float4* src = (const float4*)(emb + (size_t)id * SS);
    float4* dst = (float4*)(X0 + (size_t)row * SS);
    dst[threadIdx.x] = src[threadIdx.x];   // 256 thr * 4 = 1024
}

__global__ void zero_kernel(float* __restrict__ p, int n) {
    int i = blockIdx.x * blockDim.x + threadIdx.x;
    if (i < n) p[i] = 0.f;
}

// h_final[j][b][s] = Hj[(T-1)*16 + b][s]
__global__ void finalh_kernel(const float* __restrict__ H0,
                              const float* __restrict__ H1,
                              float* __restrict__ out) {
    int i = blockIdx.x * 256 + threadIdx.x;      // 0..32767
    const float* H = (i >> 14) ? H1 : H0;
    out[i] = H[(size_t)(TT - 1) * BB * SS + (i & 16383)];
}

// ---------------- hi/lo bf16 split conversions -----------------------------
// A: X [4096,1024] f32 -> Ab [4096,3072] bf16 as [hi | lo | hi]
__global__ void convA_kernel(const float* __restrict__ X,
                             __nv_bfloat16* __restrict__ Ab) {
    int i = (blockIdx.x * 256 + threadIdx.x) * 2;      // over 4096*1024
    int r = i >> 10, c = i & 1023;
    float2 v = *(const float2*)(X + i);
    __nv_bfloat16 h0 = __float2bfloat16(v.x);
    __nv_bfloat16 h1 = __float2bfloat16(v.y);
    __nv_bfloat16 l0 = __float2bfloat16(v.x - __bfloat162float(h0));
    __nv_bfloat16 l1 = __float2bfloat16(v.y - __bfloat162float(h1));
    __nv_bfloat162 hp; hp.x = h0; hp.y = h1;
    __nv_bfloat162 lp; lp.x = l0; lp.y = l1;
    size_t base = (size_t)r * KBIG + c;
    *(__nv_bfloat162*)(Ab + base)        = hp;
    *(__nv_bfloat162*)(Ab + base + 1024) = lp;
    *(__nv_bfloat162*)(Ab + base + 2048) = hp;
}

// B: W [1024,N] f32 (k rows, n cols) -> Bb [3072,N] bf16 as [hi ; hi ; lo]
__global__ void convB_kernel(const float* __restrict__ W,
                             __nv_bfloat16* __restrict__ Bb, int N) {
    long long i = ((long long)blockIdx.x * 256 + threadIdx.x) * 2;  // over 1024*N
    if (i >= (long long)1024 * N) return;
    int r = (int)(i / N), c = (int)(i % N);
    float2 v = *(const float2*)(W + i);
    __nv_bfloat16 h0 = __float2bfloat16(v.x);
    __nv_bfloat16 h1 = __float2bfloat16(v.y);
    __nv_bfloat16 l0 = __float2bfloat16(v.x - __bfloat162float(h0));
    __nv_bfloat16 l1 = __float2bfloat16(v.y - __bfloat162float(h1));
    __nv_bfloat162 hp; hp.x = h0; hp.y = h1;
    __nv_bfloat162 lp; lp.x = l0; lp.y = l1;
    size_t base = (size_t)r * N + c;
    *(__nv_bfloat162*)(Bb + base)                      = hp;
    *(__nv_bfloat162*)(Bb + base + (size_t)1024 * N)   = hp;
    *(__nv_bfloat162*)(Bb + base + (size_t)2048 * N)   = lp;
}

// ---------------- mma / ldmatrix primitives --------------------------------
#define LDSM_X4(R, ADDR) \
    asm volatile("ldmatrix.sync.aligned.m8n8.x4.shared.b16 {%0,%1,%2,%3}, [%4];" \
        : "=r"((R)[0]), "=r"((R)[1]), "=r"((R)[2]), "=r"((R)[3]) : "r"(ADDR))
#define LDSM_X4T(R, ADDR) \
    asm volatile("ldmatrix.sync.aligned.m8n8.x4.trans.shared.b16 {%0,%1,%2,%3}, [%4];" \
        : "=r"((R)[0]), "=r"((R)[1]), "=r"((R)[2]), "=r"((R)[3]) : "r"(ADDR))
#define LDSM_X2T(R, ADDR) \
    asm volatile("ldmatrix.sync.aligned.m8n8.x2.trans.shared.b16 {%0,%1}, [%2];" \
        : "=r"((R)[0]), "=r"((R)[1]) : "r"(ADDR))
#define MMA16816(D, Ar, B0, B1) \
    asm volatile("mma.sync.aligned.m16n8k16.row.col.f32.bf16.bf16.f32 " \
        "{%0,%1,%2,%3}, {%4,%5,%6,%7}, {%8,%9}, {%0,%1,%2,%3};" \
        : "+f"((D)[0]), "+f"((D)[1]), "+f"((D)[2]), "+f"((D)[3]) \
        : "r"((Ar)[0]), "r"((Ar)[1]), "r"((Ar)[2]), "r"((Ar)[3]), \
          "r"(B0), "r"(B1))

__device__ __forceinline__ void cpa16(unsigned dst, const void* src) {
    asm volatile("cp.async.ca.shared.global [%0], [%1], 16;" :: "r"(dst), "l"(src));
}
#define CP_COMMIT() asm volatile("cp.async.commit_group;")
#define CP_WAIT2()  asm volatile("cp.async.wait_group 2;")

// ---------------- mma.sync bf16 GEMM (cp.async 4-stage) --------------------
#define APAD 40      // 32 + 8
#define BPAD 136     // 128 + 8
#define ATILE_B (128 * APAD * 2)
#define BTILE_B (32 * BPAD * 2)
#define NSTAGE 4

__global__ __launch_bounds__(256) void gemm_bf16(
    const __nv_bfloat16* __restrict__ A, const __nv_bfloat16* __restrict__ Bm,
    const float* __restrict__ bias, float* __restrict__ C,
    int N, int remap)
{
    __shared__ __align__(16) __nv_bfloat16 As[NSTAGE][128][APAD];
    __shared__ __align__(16) __nv_bfloat16 Bs[NSTAGE][32][BPAD];

    int tid = threadIdx.x;
    int lane = tid & 31, wid = tid >> 5;
    int wm = wid & 3, wn = wid >> 2;
    int m0 = blockIdx.y * 128, n0 = blockIdx.x * 128;

    int ar0 = tid >> 2, ac0 = (tid & 3) * 8;
    int br0 = tid >> 4, bc0 = (tid & 15) * 8;
    const __nv_bfloat16* Ag  = A + (size_t)(m0 + ar0) * KBIG + ac0;
    const __nv_bfloat16* Ag2 = Ag + (size_t)64 * KBIG;
    const __nv_bfloat16* Bg  = Bm + (size_t)br0 * N + n0 + bc0;
    const __nv_bfloat16* Bg2 = Bg + (size_t)16 * N;

    unsigned sA = (unsigned)__cvta_generic_to_shared(&As[0][0][0]);
    unsigned sB = (unsigned)__cvta_generic_to_shared(&Bs[0][0][0]);
    unsigned aDst  = sA + (unsigned)((ar0 * APAD + ac0) * 2);
    unsigned aDst2 = sA + (unsigned)(((ar0 + 64) * APAD + ac0) * 2);
    unsigned bDst  = sB + (unsigned)((br0 * BPAD + bc0) * 2);
    unsigned bDst2 = sB + (unsigned)(((br0 + 16) * BPAD + bc0) * 2);

#pragma unroll
    for (int s = 0; s < NSTAGE - 1; s++) {
        int ko = s * 32;
        cpa16(aDst  + s * ATILE_B, Ag  + ko);
        cpa16(aDst2 + s * ATILE_B, Ag2 + ko);
        cpa16(bDst  + s * BTILE_B, Bg  + (size_t)ko * N);
        cpa16(bDst2 + s * BTILE_B, Bg2 + (size_t)ko * N);
        CP_COMMIT();
    }

    unsigned aBase = sA + (unsigned)(((wm * 32 + (lane & 15)) * APAD + (lane >> 4) * 8) * 2);
    unsigned bBase = sB + (unsigned)(((lane & 15) * BPAD + wn * 64 + (lane >> 4) * 8) * 2);

    float acc[2][8][4];
#pragma unroll
    for (int i = 0; i < 2; i++)
#pragma unroll
        for (int j = 0; j < 8; j++)
#pragma unroll
            for (int q = 0; q < 4; q++) acc[i][j][q] = 0.f;

    for (int kt = 0; kt < NTILES; kt++) {
        CP_WAIT2();
        __syncthreads();

        if (kt + NSTAGE - 1 < NTILES) {
            int s = (kt + NSTAGE - 1) & (NSTAGE - 1);
            int ko = (kt + NSTAGE - 1) * 32;
            cpa16(aDst  + s * ATILE_B, Ag  + ko);
            cpa16(aDst2 + s * ATILE_B, Ag2 + ko);
            cpa16(bDst  + s * BTILE_B, Bg  + (size_t)ko * N);
            cpa16(bDst2 + s * BTILE_B, Bg2 + (size_t)ko * N);
            CP_COMMIT();
        }

        int buf = kt & (NSTAGE - 1);
        unsigned aB = aBase + buf * ATILE_B;
        unsigned bB = bBase + buf * BTILE_B;
#pragma unroll
        for (int k16 = 0; k16 < 2; k16++) {
            unsigned ra[2][4], rb[4][4];
            LDSM_X4(ra[0], aB + k16 * 32);
            LDSM_X4(ra[1], aB + k16 * 32 + 16 * APAD * 2);
            LDSM_X4T(rb[0], bB + k16 * (16 * BPAD * 2));
            LDSM_X4T(rb[1], bB + k16 * (16 * BPAD * 2) + 32);
            LDSM_X4T(rb[2], bB + k16 * (16 * BPAD * 2) + 64);
            LDSM_X4T(rb[3], bB + k16 * (16 * BPAD * 2) + 96);
#pragma unroll
            for (int mi = 0; mi < 2; mi++)
#pragma unroll
                for (int ni = 0; ni < 4; ni++) {
                    MMA16816(acc[mi][2 * ni],     ra[mi], rb[ni][0], rb[ni][1]);
                    MMA16816(acc[mi][2 * ni + 1], ra[mi], rb[ni][2], rb[ni][3]);
                }
        }
    }

#pragma unroll
    for (int mi = 0; mi < 2; mi++) {
        int m = m0 + wm * 32 + mi * 16 + (lane >> 2);
#pragma unroll
        for (int h8 = 0; h8 < 2; h8++) {
            int mm = m + h8 * 8;
            size_t orow = remap ? (size_t)((mm & 15) * TT + (mm >> 4)) * N
                                : (size_t)mm * N;
#pragma unroll
            for (int nj = 0; nj < 8; nj++) {
                int col = n0 + wn * 64 + nj * 8 + (lane & 3) * 2;
                float2 v;
                v.x = acc[mi][nj][h8 * 2 + 0] + bias[col];
                v.y = acc[mi][nj][h8 * 2 + 1] + bias[col + 1];
                *(float2*)(C + orow + col) = v;
            }
        }
    }
}

// ---------------------------------------------------------------------------
// Hierarchical grid barrier (R16-proven).
// ---------------------------------------------------------------------------
__device__ __forceinline__ void grid_barrier() {
    __threadfence();
    __syncthreads();
    if (threadIdx.x == 0) {
        unsigned int gen = *((volatile unsigned int*)&g_bar_gen);
        int grp = (blockIdx.x >> 3) * 32;
        if (atomicAdd(&g_bar_grp[grp], 1u) == 7u) {
            atomicExch(&g_bar_grp[grp], 0u);
            if (atomicAdd(&g_bar_count, 1u) == 15u) {
                atomicExch(&g_bar_count, 0u);
                __threadfence();
                atomicAdd(&g_bar_gen, 1u);
            }
        }
        while (*((volatile unsigned int*)&g_bar_gen) == gen) {}
    }
    __syncthreads();
}

// ---------------------------------------------------------------------------
// Tensor-core GRU recurrence. 128 CTAs x 256 threads (8 warps).
// CTA owns 8 state cols. Weights (3 gates x 1024 k x 8 c) resident in SMEM
// as bf16 hi/lo, k-major [2048][24] (cols: z 0-7, r 8-15, n 16-23).
// Per step: [16,1024]@U -> m16 tile mma, warps split k (128 each), smem
// reduction, owner threads (tid<128: b=tid>>3, c=tid&7) hold h in registers,
// publish bf16 hi/lo h / r*h to global for all CTAs to stage.
// ---------------------------------------------------------------------------
#define WNP 24                       // wstage row width (elems); 48B rows, 16B-aligned
#define HSTR 2056                    // hstage row stride (elems); 4112B = 257*16
#define RNP 18                       // reduction row pad
#define WST_ELEMS (2048 * WNP)
#define HST_ELEMS (16 * HSTR)
#define RED_OFF   ((WST_ELEMS + HST_ELEMS) * 2)          // bytes, 16B-aligned
#define RECUR2_SMEM (RED_OFF + 8 * 16 * RNP * 4)

__global__ __launch_bounds__(256) void recur_kernel(
    const float* __restrict__ Gz, const float* __restrict__ Gr,
    const float* __restrict__ Gn,
    const float* __restrict__ Uz, const float* __restrict__ Ur,
    const float* __restrict__ Un,
    float* __restrict__ Hout,
    __nv_bfloat16* __restrict__ hbf, __nv_bfloat16* __restrict__ rhbf)
{
    extern __shared__ __align__(16) char smraw[];
    __nv_bfloat16* wst = (__nv_bfloat16*)smraw;          // [2048][WNP]
    __nv_bfloat16* hst = wst + WST_ELEMS;                // [16][HSTR]
    float* red = (float*)(smraw + RED_OFF);              // [8][16][RNP]

    int tid = threadIdx.x;
    int lane = tid & 31, wid = tid >> 5;
    int c0 = blockIdx.x * 8;

    // ---- one-time weight preload: U[k][c0+c] -> hi/lo in wst ----
    const float* Ug[3] = {Uz, Ur, Un};
    for (int i = tid; i < 3 * 8192; i += 256) {
        int g = i >> 13, rem = i & 8191;
        int k = rem >> 3, c = rem & 7;
        float v = Ug[g][(size_t)k * SS + c0 + c];
        __nv_bfloat16 hi = __float2bfloat16(v);
        __nv_bfloat16 lo = __float2bfloat16(v - __bfloat162float(hi));
        wst[k * WNP + g * 8 + c]          = hi;
        wst[(1024 + k) * WNP + g * 8 + c] = lo;
    }
    __syncthreads();

    unsigned sH = (unsigned)__cvta_generic_to_shared(hst);
    unsigned sW = (unsigned)__cvta_generic_to_shared(wst);
    // ldmatrix lane bases
    unsigned aBase = sH + (unsigned)(((lane & 15) * HSTR + (lane >> 4) * 8) * 2);
    unsigned bRow  = (unsigned)((lane & 15) * WNP * 2);  // k-row part
    unsigned bCol4 = (unsigned)((lane >> 4) * 16);       // +8 cols for lanes 16-31

    int kslc = wid * 128;
    int isOwner = (tid < 128);
    int ob = tid >> 3, oc = tid & 7;                     // owner (b, c)
    float hv = 0.f, zv = 0.f;

    for (int t = 0; t < TT; t++) {
        // ---- stage h (bf16 hi/lo, 64KB from L2) ----
        for (int i = tid; i < 4096; i += 256) {
            int row = i >> 8, col = (i & 255) * 8;
            int4 v = __ldcg((const int4*)(hbf + row * 2048 + col));
            *(int4*)(hst + row * HSTR + col) = v;
        }
        __syncthreads();

        // ---- phase 1: z, r ----
        float az[4] = {0.f, 0.f, 0.f, 0.f};
        float ar_[4] = {0.f, 0.f, 0.f, 0.f};
#pragma unroll
        for (int third = 0; third < 3; third++) {
            int aoff = (third == 1) ? 1024 : 0;          // elems (cols)
            int boff = (third == 2) ? 1024 : 0;          // k rows
#pragma unroll
            for (int kt = 0; kt < 8; kt++) {
                int k = kslc + kt * 16;
                unsigned ra[4], rb[4];
                LDSM_X4(ra, aBase + (unsigned)((aoff + k) * 2));
                LDSM_X4T(rb, sW + (unsigned)((boff + k) * WNP * 2) + bRow + bCol4);
                MMA16816(az,  ra, rb[0], rb[1]);         // cols 0-7  (z)
                MMA16816(ar_, ra, rb[2], rb[3]);         // cols 8-15 (r)
            }
        }
        {
            int m0 = lane >> 2, nn = (lane & 3) * 2;
            float* rw = red + (wid * 16) * RNP;
            rw[m0 * RNP + nn]           = az[0];
            rw[m0 * RNP + nn + 1]       = az[1];
            rw[(m0 + 8) * RNP + nn]     = az[2];
            rw[(m0 + 8) * RNP + nn + 1] = az[3];
            rw[m0 * RNP + 8 + nn]           = ar_[0];
            rw[m0 * RNP + 8 + nn + 1]       = ar_[1];
            rw[(m0 + 8) * RNP + 8 + nn]     = ar_[2];
            rw[(m0 + 8) * RNP + 8 + nn + 1] = ar_[3];
        }
        __syncthreads();

        if (isOwner) {
            float z = 0.f, r = 0.f;
#pragma unroll
            for (int w = 0; w < 8; w++) {
                z += red[(w * 16 + ob) * RNP + oc];
                r += red[(w * 16 + ob) * RNP + 8 + oc];
            }
            size_t grow = (size_t)(t * BB + ob) * SS + c0 + oc;
            z += Gz[grow];
            r += Gr[grow];
            zv = 1.f / (1.f + expf(-z));
            float rv = 1.f / (1.f + expf(-r));
            float rh = rv * hv;
            __nv_bfloat16 hi = __float2bfloat16(rh);
            __nv_bfloat16 lo = __float2bfloat16(rh - __bfloat162float(hi));
            rhbf[ob * 2048 + c0 + oc]        = hi;
            rhbf[ob * 2048 + 1024 + c0 + oc] = lo;
        }
        grid_barrier();

        // ---- stage rh ----
        for (int i = tid; i < 4096; i += 256) {
            int row = i >> 8, col = (i & 255) * 8;
            int4 v = __ldcg((const int4*)(rhbf + row * 2048 + col));
            *(int4*)(hst + row * HSTR + col) = v;
        }
        __syncthreads();

        // ---- phase 2: n ----
        float an[4] = {0.f, 0.f, 0.f, 0.f};
#pragma unroll
        for (int third = 0; third < 3; third++) {
            int aoff = (third == 1) ? 1024 : 0;
            int boff = (third == 2) ? 1024 : 0;
#pragma unroll
            for (int kt = 0; kt < 8; kt++) {
                int k = kslc + kt * 16;
                unsigned ra[4], rb2[2];
                LDSM_X4(ra, aBase + (unsigned)((aoff + k) * 2));
                LDSM_X2T(rb2, sW + (unsigned)(((boff + k) * WNP + 16) * 2) + bRow);
                MMA16816(an, ra, rb2[0], rb2[1]);        // cols 16-23 (n)
            }
        }
        {
            int m0 = lane >> 2, nn = (lane & 3) * 2;
            float* rw = red + (wid * 16) * RNP;
            rw[m0 * RNP + nn]           = an[0];
            rw[m0 * RNP + nn + 1]       = an[1];
            rw[(m0 + 8) * RNP + nn]     = an[2];
            rw[(m0 + 8) * RNP + nn + 1] = an[3];
        }
        __syncthreads();

        if (isOwner) {
            float n = 0.f;
#pragma unroll
            for (int w = 0; w < 8; w++)
                n += red[(w * 16 + ob) * RNP + oc];
            size_t grow = (size_t)(t * BB + ob) * SS + c0 + oc;
            n += Gn[grow];
            float nv = tanhf(n);
            float hn = (1.f - zv) * hv + zv * nv;
            hv = hn;
            __nv_bfloat16 hi = __float2bfloat16(hn);
            __nv_bfloat16 lo = __float2bfloat16(hn - __bfloat162float(hi));
            hbf[ob * 2048 + c0 + oc]        = hi;
            hbf[ob * 2048 + 1024 + c0 + oc] = lo;
            Hout[grow] = hn;
        }
        grid_barrier();
    }
}

// ---------------------------------------------------------------------------
extern "C" void kernel_launch(void* const* d_in, const int* in_sizes, int n_in,
                              void* d_out, int out_size) {
    const int*   x   = (const int*)  d_in[0];
    const float* emb = (const float*)d_in[1];
    const float* Wz  = (const float*)d_in[2];
    const float* bz  = (const float*)d_in[3];
    const float* Wr  = (const float*)d_in[4];
    const float* br  = (const float*)d_in[5];
    const float* Wn  = (const float*)d_in[6];
    const float* bn  = (const float*)d_in[7];
    const float* Wo  = (const float*)d_in[8];
    const float* bo  = (const float*)d_in[9];
    float* out = (float*)d_out;

    float* s = nullptr;
    cudaGetSymbolAddress((void**)&s, g_scratch);
    float* X0 = s;
    float* Gz = X0 + 4194304;
    float* Gr = Gz + 4194304;
    float* Gn = Gr + 4194304;
    float* H0 = Gn + 4194304;
    float* H1 = H0 + 4194304;

    __nv_bfloat16* bf = nullptr;
    cudaGetSymbolAddress((void**)&bf, g_bf);
    __nv_bfloat16* Ab  = bf;
    __nv_bfloat16* bWo = Ab + ABIG_ELEMS;
    __nv_bfloat16* bG[6];
    for (int g = 0; g < 6; g++) bG[g] = bWo + BWO_ELEMS + (size_t)g * BG_ELEMS;

    __nv_bfloat16* hbf = nullptr;
    cudaGetSymbolAddress((void**)&hbf, g_hbf);
    __nv_bfloat16* rhbf = nullptr;
    cudaGetSymbolAddress((void**)&rhbf, g_rhbf);

    cudaFuncSetAttribute(recur_kernel,
                         cudaFuncAttributeMaxDynamicSharedMemorySize, RECUR2_SMEM);

    // Wz/Wr/Wn layout: [L][E+S][S]. Input rows 0..1023; hidden rows 1024..2047.
    const size_t L0_IN  = 0;
    const size_t L0_HID = (size_t)1024 * 1024;
    const size_t L1_IN  = (size_t)2048 * 1024;
    const size_t L1_HID = (size_t)3072 * 1024;

    // weight conversions (hi/lo split, every call — no caching)
    const int gbGate = (1024 * 1024 / 2 + 255) / 256;          // 2048
    convB_kernel<<<gbGate, 256>>>(Wz + L0_IN, bG[0], SS);
    convB_kernel<<<gbGate, 256>>>(Wr + L0_IN, bG[1], SS);
    convB_kernel<<<gbGate, 256>>>(Wn + L0_IN, bG[2], SS);
    convB_kernel<<<gbGate, 256>>>(Wz + L1_IN, bG[3], SS);
    convB_kernel<<<gbGate, 256>>>(Wr + L1_IN, bG[4], SS);
    convB_kernel<<<gbGate, 256>>>(Wn + L1_IN, bG[5], SS);
    const long long woElems = (long long)1024 * VV;
    convB_kernel<<<(unsigned)((woElems / 2 + 255) / 256), 256>>>(Wo, bWo, VV);

    embed_kernel<<<MM, 256>>>(x, emb, X0);

    const int gbA = MM * SS / 2 / 256;                          // 8192
    dim3 gg(SS / 128, MM / 128);                                // (8, 32)

    // layer 0
    convA_kernel<<<gbA, 256>>>(X0, Ab);
    gemm_bf16<<<gg, 256>>>(Ab, bG[0], bz,      Gz, SS, 0);
    gemm_bf16<<<gg, 256>>>(Ab, bG[1], br,      Gr, SS, 0);
    gemm_bf16<<<gg, 256>>>(Ab, bG[2], bn,      Gn, SS, 0);
    zero_kernel<<<64, 256>>>((float*)hbf, 16384);               // 16*2048 bf16
    recur_kernel<<<NB_RECUR, 256, RECUR2_SMEM>>>(Gz, Gr, Gn,
        Wz + L0_HID, Wr + L0_HID, Wn + L0_HID, H0, hbf, rhbf);

    // layer 1
    convA_kernel<<<gbA, 256>>>(H0, Ab);
    gemm_bf16<<<gg, 256>>>(Ab, bG[3], bz + SS, Gz, SS, 0);
    gemm_bf16<<<gg, 256>>>(Ab, bG[4], br + SS, Gr, SS, 0);
    gemm_bf16<<<gg, 256>>>(Ab, bG[5], bn + SS, Gn, SS, 0);
    zero_kernel<<<64, 256>>>((float*)hbf, 16384);
    recur_kernel<<<NB_RECUR, 256, RECUR2_SMEM>>>(Gz, Gr, Gn,
        Wz + L1_HID, Wr + L1_HID, Wn + L1_HID, H1, hbf, rhbf);

    // output projection with (t,b)->(b,t) remap
    convA_kernel<<<gbA, 256>>>(H1, Ab);
    dim3 go(VV / 128, MM / 128);                                // (250, 32)
    gemm_bf16<<<go, 256>>>(Ab, bWo, bo, out, VV, 1);

    if (out_size >= OUT_ELEMS + 2 * BB * SS)
        finalh_kernel<<<128, 256>>>(H0, H1, out + OUT_ELEMS);
}